// round 8
// baseline (speedup 1.0000x reference)
#include <cuda_runtime.h>
#include <cstdint>

// ---------------------------------------------------------------------------
// EncoderGRU: bidirectional GRU, SEQ=4096, HIDDEN=EMBED=1024.
//
//   Phase 1+2 (one kernel): GI[t] = w_ih @ emb[tok[t]] + b_ih, fp32 SIMT GEMM,
//            with inline token prep + recurrent-state reset by block (0,0).
//   Phase 3: persistent kernel, 128 CTAs. fwd and bwd share w_hh (one GRU
//            cell), so EACH CTA owns 8 hidden units of BOTH directions:
//            24 shared weight rows (96KB smem). Warps 0-3 = fwd engine,
//            warps 4-7 = bwd engine, decoupled via named barriers. While one
//            engine waits for its direction's counter to propagate through
//            L2, the other engine computes on the same SM -> the cross-SM
//            sync latency (the dominant cost per ncu: issue=11%, L1=26%) is
//            hidden behind compute of the opposite direction.
//            Per-direction sync protocol is VERBATIM round-7 (proven):
//            producer stcg h -> group barrier -> one thread fence + REDG;
//            consumer: every thread first-check + nanosleep-poll + own
//            threadfence before ldcg h. Fan-in now 128 (need = s<<7).
// ---------------------------------------------------------------------------

#define VOCAB   50257
#define HID     1024
#define SEQ     4096
#define NROWS   (SEQ + 2)       // 4098: +SOS row, +EOS row
#define GATES   3072

#define NCTA    128             // persistent grid (1 CTA/SM)
#define UPD     8               // units per direction per CTA (128*8 = 1024)
#define RPD     24              // weight rows per CTA (3 gates x 8 units, shared by dirs)
#define GT      256             // threads (warps 0-3 fwd, warps 4-7 bwd)
#define RPW     6               // rows per warp (4 warps/half * 6 = 24)

// ---- global scratch (allocation-free: __device__ globals) ----
__device__ __align__(16)  float g_GI[(size_t)NROWS * GATES];    // ~50 MB
__device__ __align__(16)  float g_h[2][2][HID];                 // [dir][buf][unit]
__device__ __align__(128) int   g_cnt[2][32];                   // one 128B line per dir

__device__ __forceinline__ int ldcg_int(const int* p) {
    int v;
    asm volatile("ld.global.cg.b32 %0, [%1];" : "=r"(v) : "l"(p));
    return v;
}

// ---------------------------------------------------------------------------
// Phase 1+2: GI GEMM with inline token prep + state reset.
// C[m][n] = sum_k emb[tok[m]][k] * w_ih[n][k] + b_ih[n]
// BM=BN=128, BK=8, 256 threads, 8x8 microtile per thread.
// ---------------------------------------------------------------------------
#define BM 128
#define BN 128
#define BK 8

__global__ void __launch_bounds__(256) gi_gemm_kernel(
    const void*  __restrict__ tok_raw,
    const float* __restrict__ emb,
    const float* __restrict__ w_ih,
    const float* __restrict__ b_ih) {

    __shared__ float As[BK][BM];
    __shared__ float Bs[BK][BN];
    __shared__ int   mode64_sh;

    const int tid  = threadIdx.x;
    const int m0   = blockIdx.y * BM;
    const int n0   = blockIdx.x * BN;
    const int lrow = tid >> 1;          // 0..127
    const int lk   = (tid & 1) * 4;     // 0 or 4
    const int tx   = tid & 15;
    const int ty   = tid >> 4;

    // state reset (fresh every launch / graph replay) -- block (0,0) only
    if (blockIdx.x == 0 && blockIdx.y == 0) {
        for (int i = tid; i < 2 * 2 * HID; i += 256) ((float*)g_h)[i] = 0.f;
        if (tid < 64) ((int*)g_cnt)[tid] = 0;
    }

    // token dtype detection (per block; 8 loads, trivial)
    if (tid == 0) {
        // Genuine int64 tokens: every value < VOCAB (high word 0).
        // int32 data misread as int64: some 64-bit word >= VOCAB w.h.p.
        const unsigned long long* p = (const unsigned long long*)tok_raw;
        int m = 1;
        #pragma unroll
        for (int i = 0; i < 8; i++)
            if (p[i] >= (unsigned long long)VOCAB) m = 0;
        mode64_sh = m;
    }
    __syncthreads();
    const int mode64 = mode64_sh;

    // inline token fetch for this block's A row
    const int m = m0 + lrow;
    const float* arow_ptr = nullptr;
    if (m < NROWS) {
        int tok;
        if (m == SEQ)          tok = 0;   // SOS
        else if (m == SEQ + 1) tok = 1;   // EOS
        else tok = mode64 ? (int)((const long long*)tok_raw)[m]
                          : ((const int*)tok_raw)[m];
        arow_ptr = emb + (size_t)tok * HID;
    }
    const float* brow_ptr = w_ih + (size_t)(n0 + lrow) * HID;

    float acc[8][8];
    #pragma unroll
    for (int i = 0; i < 8; i++)
        #pragma unroll
        for (int j = 0; j < 8; j++) acc[i][j] = 0.f;

    for (int k0 = 0; k0 < HID; k0 += BK) {
        float4 a4 = make_float4(0.f, 0.f, 0.f, 0.f);
        if (arow_ptr) a4 = *(const float4*)(arow_ptr + k0 + lk);
        float4 b4 = *(const float4*)(brow_ptr + k0 + lk);
        As[lk + 0][lrow] = a4.x; As[lk + 1][lrow] = a4.y;
        As[lk + 2][lrow] = a4.z; As[lk + 3][lrow] = a4.w;
        Bs[lk + 0][lrow] = b4.x; Bs[lk + 1][lrow] = b4.y;
        Bs[lk + 2][lrow] = b4.z; Bs[lk + 3][lrow] = b4.w;
        __syncthreads();

        #pragma unroll
        for (int kk = 0; kk < BK; kk++) {
            float ra[8], rb[8];
            *(float4*)&ra[0] = *(const float4*)&As[kk][ty * 8];
            *(float4*)&ra[4] = *(const float4*)&As[kk][ty * 8 + 4];
            *(float4*)&rb[0] = *(const float4*)&Bs[kk][tx * 8];
            *(float4*)&rb[4] = *(const float4*)&Bs[kk][tx * 8 + 4];
            #pragma unroll
            for (int i = 0; i < 8; i++)
                #pragma unroll
                for (int j = 0; j < 8; j++)
                    acc[i][j] += ra[i] * rb[j];
        }
        __syncthreads();
    }

    float bias[8];
    *(float4*)&bias[0] = *(const float4*)(b_ih + n0 + tx * 8);
    *(float4*)&bias[4] = *(const float4*)(b_ih + n0 + tx * 8 + 4);

    #pragma unroll
    for (int i = 0; i < 8; i++) {
        int mm = m0 + ty * 8 + i;
        if (mm < NROWS) {
            float* gp = g_GI + (size_t)mm * GATES + n0 + tx * 8;
            float4 v0 = make_float4(acc[i][0] + bias[0], acc[i][1] + bias[1],
                                    acc[i][2] + bias[2], acc[i][3] + bias[3]);
            float4 v1 = make_float4(acc[i][4] + bias[4], acc[i][5] + bias[5],
                                    acc[i][6] + bias[6], acc[i][7] + bias[7]);
            *(float4*)gp       = v0;
            *(float4*)(gp + 4) = v1;
        }
    }
}

// ---------------------------------------------------------------------------
// Phase 3: persistent recurrent kernel, dual-direction engines per CTA.
// ---------------------------------------------------------------------------
__global__ void __launch_bounds__(GT, 1) gru_seq_kernel(
    const float* __restrict__ w_hh,
    const float* __restrict__ b_hh,
    float* __restrict__ out) {

    extern __shared__ float smem[];
    float* wsh   = smem;                // RPD * HID weights (shared by dirs)
    float* bsh   = wsh + RPD * HID;     // RPD biases
    float* sums2 = bsh + RPD;           // 2 * RPD partial sums [half][row]

    const int cta  = blockIdx.x;
    const int u0   = cta * UPD;         // this CTA's 8 units (both dirs)
    const int tid  = threadIdx.x;
    const int warp = tid >> 5;
    const int lane = tid & 31;
    const int half = warp >> 2;         // 0 = fwd engine, 1 = bwd engine
    const int hwarp = warp & 3;         // warp index within the engine
    const int dir  = half;
    float* sums = sums2 + half * RPD;

    // Load this CTA's 24 w_hh rows (gate-major: row rr -> gate rr>>3, unit rr&7)
    for (int i = tid; i < RPD * HID; i += GT) {
        int rr = i >> 10;
        int c  = i & (HID - 1);
        int grow = ((rr >> 3) << 10) + u0 + (rr & 7);
        wsh[i] = w_hh[(size_t)grow * HID + c];
    }
    if (tid < RPD) bsh[tid] = b_hh[((tid >> 3) << 10) + u0 + (tid & 7)];
    __syncthreads();

    const float* wp    = wsh + hwarp * RPW * HID + lane * 4;
    const int*   cnt_p = &g_cnt[dir][0];
    const int    barid = 1 + half;      // named barriers 1 (fwd) / 2 (bwd)

    float hprev = 0.f;                  // engine warp 0, lanes < UPD

    for (int s = 0; s <= SEQ; s++) {
        const int t     = dir ? (SEQ - s) : (s - 1);
        const int girow = (s == 0) ? (SEQ + dir) : t;

        // gi prefetch (independent of h; overlaps the poll below)
        float gir = 0.f, giz = 0.f, gin = 0.f;
        if (hwarp == 0 && lane < UPD) {
            const float* gp = g_GI + (size_t)girow * GATES + u0 + lane;
            gir = __ldg(gp);
            giz = __ldg(gp + HID);
            gin = __ldg(gp + 2 * HID);
        }

        // Wait until all 128 CTAs published this direction's step s-1.
        // Every thread first-check + nanosleep-poll + own fence (r7 proven).
        // With the two engines antiphased, the first check normally passes.
        if (s > 0) {
            const int need = s << 7;    // 128 * s
            if (ldcg_int(cnt_p) < need) {
                do { __nanosleep(60); } while (ldcg_int(cnt_p) < need);
            }
            __threadfence();            // acquire (per-thread)
        }

        // load broadcast h of this direction (L2)
        const float4* hp = (const float4*)(&g_h[dir][s & 1][0]) + lane;
        float4 h4[8];
        #pragma unroll
        for (int j = 0; j < 8; j++) h4[j] = __ldcg(hp + 32 * j);

        // 6 dot products per warp, lanes stride columns by 4
        float acc[RPW] = {0.f, 0.f, 0.f, 0.f, 0.f, 0.f};
        #pragma unroll
        for (int j = 0; j < 8; j++) {
            const float4 hv = h4[j];
            #pragma unroll
            for (int r = 0; r < RPW; r++) {
                const float4 wv = *(const float4*)(wp + r * HID + j * 128);
                acc[r] += hv.x * wv.x;
                acc[r] += hv.y * wv.y;
                acc[r] += hv.z * wv.z;
                acc[r] += hv.w * wv.w;
            }
        }
        #pragma unroll
        for (int r = 0; r < RPW; r++) {
            float v = acc[r];
            v += __shfl_xor_sync(0xffffffffu, v, 16);
            v += __shfl_xor_sync(0xffffffffu, v, 8);
            v += __shfl_xor_sync(0xffffffffu, v, 4);
            v += __shfl_xor_sync(0xffffffffu, v, 2);
            v += __shfl_xor_sync(0xffffffffu, v, 1);
            if (lane == 0) sums[hwarp * RPW + r] = v;
        }
        // engine-scope barrier: sums of this half ready
        asm volatile("bar.sync %0, 128;" :: "r"(barid) : "memory");

        if (hwarp == 0 && lane < UPD) {
            const int u = u0 + lane;
            float rg = 1.f / (1.f + __expf(-(gir + sums[lane]     + bsh[lane])));
            float zg = 1.f / (1.f + __expf(-(giz + sums[8 + lane] + bsh[8 + lane])));
            float ng = tanhf(gin + rg * (sums[16 + lane] + bsh[16 + lane]));
            float hn = (1.f - zg) * ng + zg * hprev;
            hprev = hn;
            __stcg(&g_h[dir][(s + 1) & 1][u], hn);
            if (s >= 1) {
                // hiddens[t] = [hs_f[t] | hs_b[t]], after h_b (1024 floats)
                out[(size_t)HID + (size_t)t * (2 * HID) + dir * HID + u] = hn;
                if (dir == 1 && t == 0) out[u] = hn;   // h_b = hs_b[0]
            }
        }
        // engine-scope barrier: h writes visible within the engine
        asm volatile("bar.sync %0, 128;" :: "r"(barid) : "memory");
        if (tid == half * 128) {
            __threadfence();            // cumulative release: h before counter
            atomicAdd(&g_cnt[dir][0], 1);   // REDG (result unused)
        }
    }
}

// ---------------------------------------------------------------------------
// launch
// ---------------------------------------------------------------------------
extern "C" void kernel_launch(void* const* d_in, const int* in_sizes, int n_in,
                              void* d_out, int out_size) {
    const void*  tokens = d_in[0];
    const float* emb    = (const float*)d_in[1];
    const float* w_ih   = (const float*)d_in[2];
    const float* w_hh   = (const float*)d_in[3];
    const float* b_ih   = (const float*)d_in[4];
    const float* b_hh   = (const float*)d_in[5];
    float* out = (float*)d_out;

    const int smem_bytes = (RPD * HID + 3 * RPD + 16) * (int)sizeof(float);
    cudaFuncSetAttribute(gru_seq_kernel,
                         cudaFuncAttributeMaxDynamicSharedMemorySize,
                         smem_bytes);

    dim3 ggrid(GATES / BN, (NROWS + BM - 1) / BM);
    gi_gemm_kernel<<<ggrid, 256>>>(tokens, emb, w_ih, b_ih);

    gru_seq_kernel<<<NCTA, GT, smem_bytes>>>(w_hh, b_hh, out);
}

// round 9
// speedup vs baseline: 1.1059x; 1.1059x over previous
#include <cuda_runtime.h>
#include <cstdint>

// ---------------------------------------------------------------------------
// EncoderGRU: bidirectional GRU, SEQ=4096, HIDDEN=EMBED=1024.
//
//   Phase 1+2 (one kernel): GI[t] = w_ih @ emb[tok[t]] + b_ih, fp32 SIMT GEMM,
//            inline token prep + recurrent-state reset by block (0,0).
//   Phase 3: persistent kernel, 128 CTAs (64 fwd / 64 bwd), each CTA owns 16
//            hidden units (48 w_hh rows). NEW vs r7: 4 of each warp's 6 rows
//            live in REGISTERS (128 regs/thread, loaded once); only 2 rows/warp
//            stream from smem per step. LDS traffic/step: 192KB -> 64KB; the
//            matvec becomes FFMA-bound (~768 cyc) instead of LDS-bound (1536).
//            Sync protocol is VERBATIM round-7 (proven): producer gates ->
//            stcg h -> __syncthreads -> thread0 fence + REDG counter;
//            consumer: every thread first-check + nanosleep-poll + own
//            threadfence before ldcg h.
// ---------------------------------------------------------------------------

#define VOCAB   50257
#define HID     1024
#define SEQ     4096
#define NROWS   (SEQ + 2)       // 4098: +SOS row, +EOS row
#define GATES   3072

#define NCTA    128             // persistent grid (1 CTA/SM)
#define UNITS   16              // hidden units per CTA (64 CTAs/dir * 16 = 1024)
#define RPC     48              // weight rows per CTA (3 gates * 16 units)
#define GT      256             // threads in recurrent kernel
#define RPW     6               // rows per warp (8 warps * 6 = 48)
#define RREG    4               // rows per warp held in registers
#define RSM     2               // rows per warp streamed from smem (RPW-RREG)

// ---- global scratch (allocation-free: __device__ globals) ----
__device__ __align__(16)  float g_GI[(size_t)NROWS * GATES];    // ~50 MB
__device__ __align__(16)  float g_h[2][2][HID];                 // [dir][buf][unit]
__device__ __align__(128) int   g_cnt[2][32];                   // one 128B line per dir

__device__ __forceinline__ int ldcg_int(const int* p) {
    int v;
    asm volatile("ld.global.cg.b32 %0, [%1];" : "=r"(v) : "l"(p));
    return v;
}

// ---------------------------------------------------------------------------
// Phase 1+2: GI GEMM with inline token prep + state reset.
// C[m][n] = sum_k emb[tok[m]][k] * w_ih[n][k] + b_ih[n]
// BM=BN=128, BK=8, 256 threads, 8x8 microtile per thread.
// ---------------------------------------------------------------------------
#define BM 128
#define BN 128
#define BK 8

__global__ void __launch_bounds__(256) gi_gemm_kernel(
    const void*  __restrict__ tok_raw,
    const float* __restrict__ emb,
    const float* __restrict__ w_ih,
    const float* __restrict__ b_ih) {

    __shared__ float As[BK][BM];
    __shared__ float Bs[BK][BN];
    __shared__ int   mode64_sh;

    const int tid  = threadIdx.x;
    const int m0   = blockIdx.y * BM;
    const int n0   = blockIdx.x * BN;
    const int lrow = tid >> 1;          // 0..127
    const int lk   = (tid & 1) * 4;     // 0 or 4
    const int tx   = tid & 15;
    const int ty   = tid >> 4;

    // state reset (fresh every launch / graph replay) -- block (0,0) only
    if (blockIdx.x == 0 && blockIdx.y == 0) {
        for (int i = tid; i < 2 * 2 * HID; i += 256) ((float*)g_h)[i] = 0.f;
        if (tid < 64) ((int*)g_cnt)[tid] = 0;
    }

    // token dtype detection (per block; 8 loads, trivial)
    if (tid == 0) {
        // Genuine int64 tokens: every value < VOCAB (high word 0).
        // int32 data misread as int64: some 64-bit word >= VOCAB w.h.p.
        const unsigned long long* p = (const unsigned long long*)tok_raw;
        int m = 1;
        #pragma unroll
        for (int i = 0; i < 8; i++)
            if (p[i] >= (unsigned long long)VOCAB) m = 0;
        mode64_sh = m;
    }
    __syncthreads();
    const int mode64 = mode64_sh;

    // inline token fetch for this block's A row
    const int m = m0 + lrow;
    const float* arow_ptr = nullptr;
    if (m < NROWS) {
        int tok;
        if (m == SEQ)          tok = 0;   // SOS
        else if (m == SEQ + 1) tok = 1;   // EOS
        else tok = mode64 ? (int)((const long long*)tok_raw)[m]
                          : ((const int*)tok_raw)[m];
        arow_ptr = emb + (size_t)tok * HID;
    }
    const float* brow_ptr = w_ih + (size_t)(n0 + lrow) * HID;

    float acc[8][8];
    #pragma unroll
    for (int i = 0; i < 8; i++)
        #pragma unroll
        for (int j = 0; j < 8; j++) acc[i][j] = 0.f;

    for (int k0 = 0; k0 < HID; k0 += BK) {
        float4 a4 = make_float4(0.f, 0.f, 0.f, 0.f);
        if (arow_ptr) a4 = *(const float4*)(arow_ptr + k0 + lk);
        float4 b4 = *(const float4*)(brow_ptr + k0 + lk);
        As[lk + 0][lrow] = a4.x; As[lk + 1][lrow] = a4.y;
        As[lk + 2][lrow] = a4.z; As[lk + 3][lrow] = a4.w;
        Bs[lk + 0][lrow] = b4.x; Bs[lk + 1][lrow] = b4.y;
        Bs[lk + 2][lrow] = b4.z; Bs[lk + 3][lrow] = b4.w;
        __syncthreads();

        #pragma unroll
        for (int kk = 0; kk < BK; kk++) {
            float ra[8], rb[8];
            *(float4*)&ra[0] = *(const float4*)&As[kk][ty * 8];
            *(float4*)&ra[4] = *(const float4*)&As[kk][ty * 8 + 4];
            *(float4*)&rb[0] = *(const float4*)&Bs[kk][tx * 8];
            *(float4*)&rb[4] = *(const float4*)&Bs[kk][tx * 8 + 4];
            #pragma unroll
            for (int i = 0; i < 8; i++)
                #pragma unroll
                for (int j = 0; j < 8; j++)
                    acc[i][j] += ra[i] * rb[j];
        }
        __syncthreads();
    }

    float bias[8];
    *(float4*)&bias[0] = *(const float4*)(b_ih + n0 + tx * 8);
    *(float4*)&bias[4] = *(const float4*)(b_ih + n0 + tx * 8 + 4);

    #pragma unroll
    for (int i = 0; i < 8; i++) {
        int mm = m0 + ty * 8 + i;
        if (mm < NROWS) {
            float* gp = g_GI + (size_t)mm * GATES + n0 + tx * 8;
            float4 v0 = make_float4(acc[i][0] + bias[0], acc[i][1] + bias[1],
                                    acc[i][2] + bias[2], acc[i][3] + bias[3]);
            float4 v1 = make_float4(acc[i][4] + bias[4], acc[i][5] + bias[5],
                                    acc[i][6] + bias[6], acc[i][7] + bias[7]);
            *(float4*)gp       = v0;
            *(float4*)(gp + 4) = v1;
        }
    }
}

// ---------------------------------------------------------------------------
// Phase 3: persistent recurrent kernel.
// Weight rows per warp: rows 0..3 in registers, rows 4..5 in smem.
// Global row for local row rr (0..47): ((rr>>4)<<10) + u0 + (rr&15).
// Column set per lane: { lane*4 + j*128 + k : j in 0..7, k in 0..3 }.
// ---------------------------------------------------------------------------
__global__ void __launch_bounds__(GT, 1) gru_seq_kernel(
    const float* __restrict__ w_hh,
    const float* __restrict__ b_hh,
    float* __restrict__ out) {

    extern __shared__ float smem[];
    float* wsh  = smem;                 // 16 rows (2/warp) * HID
    float* bsh  = smem + (RSM * 8) * HID;   // RPC biases
    float* sums = bsh + RPC;            // RPC partial sums

    const int cta  = blockIdx.x;
    const int dir  = cta >> 6;          // 0 = forward, 1 = backward
    const int lcta = cta & 63;
    const int u0   = lcta * UNITS;
    const int warp = threadIdx.x >> 5;
    const int lane = threadIdx.x & 31;

    // --- smem rows: local rows {w*6+4, w*6+5} stored at smem row (w*2 + sub)
    for (int i = threadIdx.x; i < RSM * 8 * HID; i += GT) {
        int mrow = i >> 10;             // 0..15
        int c    = i & (HID - 1);
        int rr   = (mrow >> 1) * RPW + RREG + (mrow & 1);
        int grow = ((rr >> 4) << 10) + u0 + (rr & 15);
        wsh[i] = w_hh[(size_t)grow * HID + c];
    }
    if (threadIdx.x < RPC) {
        int rr = threadIdx.x;
        bsh[rr] = b_hh[((rr >> 4) << 10) + u0 + (rr & 15)];
    }

    // --- register rows: warp's local rows 0..3, this lane's 32 columns
    float4 wreg[RREG][8];
    #pragma unroll
    for (int r = 0; r < RREG; r++) {
        const int rr   = warp * RPW + r;
        const int grow = ((rr >> 4) << 10) + u0 + (rr & 15);
        const float* gw = w_hh + (size_t)grow * HID + lane * 4;
        #pragma unroll
        for (int j = 0; j < 8; j++)
            wreg[r][j] = *(const float4*)(gw + j * 128);
    }
    __syncthreads();

    const float* wp = wsh + (warp * RSM) * HID + lane * 4;  // smem rows 4..5
    const int* cnt_p = &g_cnt[dir][0];

    float hprev = 0.f;                  // held by threads < UNITS only

    for (int s = 0; s <= SEQ; s++) {
        const int t     = dir ? (SEQ - s) : (s - 1);
        const int girow = (s == 0) ? (SEQ + dir) : t;

        // gi prefetch (independent of h; overlaps the poll below)
        float gir = 0.f, giz = 0.f, gin = 0.f;
        if (threadIdx.x < UNITS) {
            const float* gp = g_GI + (size_t)girow * GATES + u0 + threadIdx.x;
            gir = __ldg(gp);
            giz = __ldg(gp + HID);
            gin = __ldg(gp + 2 * HID);
        }

        // Wait until all 64 CTAs of this direction finished step s-1.
        // EVERY thread observes the counter itself (broadcast 4B sector) and
        // fences itself -- the proven acquire pattern (r5/r7). nanosleep
        // backoff keeps the hot sector below its L2 service capacity.
        if (s > 0) {
            const int need = s << 6;    // 64 * s
            if (ldcg_int(cnt_p) < need) {
                do { __nanosleep(60); } while (ldcg_int(cnt_p) < need);
            }
            __threadfence();            // acquire (per-thread)
        }

        // load broadcast h (L2: written by other SMs last step)
        const float4* hp = (const float4*)(&g_h[dir][s & 1][0]) + lane;
        float4 h4[8];
        #pragma unroll
        for (int j = 0; j < 8; j++) h4[j] = __ldcg(hp + 32 * j);

        // 6 dot products per warp: rows 0..3 from registers, 4..5 from smem
        float acc[RPW] = {0.f, 0.f, 0.f, 0.f, 0.f, 0.f};
        #pragma unroll
        for (int j = 0; j < 8; j++) {
            const float4 hv = h4[j];
            #pragma unroll
            for (int r = 0; r < RREG; r++) {
                const float4 wv = wreg[r][j];
                acc[r] += hv.x * wv.x;
                acc[r] += hv.y * wv.y;
                acc[r] += hv.z * wv.z;
                acc[r] += hv.w * wv.w;
            }
            #pragma unroll
            for (int r = 0; r < RSM; r++) {
                const float4 wv = *(const float4*)(wp + r * HID + j * 128);
                acc[RREG + r] += hv.x * wv.x;
                acc[RREG + r] += hv.y * wv.y;
                acc[RREG + r] += hv.z * wv.z;
                acc[RREG + r] += hv.w * wv.w;
            }
        }
        #pragma unroll
        for (int r = 0; r < RPW; r++) {
            float v = acc[r];
            v += __shfl_xor_sync(0xffffffffu, v, 16);
            v += __shfl_xor_sync(0xffffffffu, v, 8);
            v += __shfl_xor_sync(0xffffffffu, v, 4);
            v += __shfl_xor_sync(0xffffffffu, v, 2);
            v += __shfl_xor_sync(0xffffffffu, v, 1);
            if (lane == 0) sums[warp * RPW + r] = v;
        }
        __syncthreads();                // sums ready

        if (threadIdx.x < UNITS) {
            const int i = threadIdx.x;
            const int u = u0 + i;
            float rg = 1.f / (1.f + __expf(-(gir + sums[i]      + bsh[i])));
            float zg = 1.f / (1.f + __expf(-(giz + sums[16 + i] + bsh[16 + i])));
            float ng = tanhf(gin + rg * (sums[32 + i] + bsh[32 + i]));
            float hn = (1.f - zg) * ng + zg * hprev;
            hprev = hn;
            __stcg(&g_h[dir][(s + 1) & 1][u], hn);
            if (s >= 1) {
                // hiddens[t] = [hs_f[t] | hs_b[t]], after h_b (1024 floats)
                out[(size_t)HID + (size_t)t * (2 * HID) + dir * HID + u] = hn;
                if (dir == 1 && t == 0) out[u] = hn;   // h_b = hs_b[0]
            }
        }
        __syncthreads();                // h writes CTA-visible (r7 pattern)
        if (threadIdx.x == 0) {
            __threadfence();            // cumulative release: h before counter
            atomicAdd(&g_cnt[dir][0], 1);  // REDG (result unused)
        }
    }
}

// ---------------------------------------------------------------------------
// launch
// ---------------------------------------------------------------------------
extern "C" void kernel_launch(void* const* d_in, const int* in_sizes, int n_in,
                              void* d_out, int out_size) {
    const void*  tokens = d_in[0];
    const float* emb    = (const float*)d_in[1];
    const float* w_ih   = (const float*)d_in[2];
    const float* w_hh   = (const float*)d_in[3];
    const float* b_ih   = (const float*)d_in[4];
    const float* b_hh   = (const float*)d_in[5];
    float* out = (float*)d_out;

    const int smem_bytes = (RSM * 8 * HID + 2 * RPC + 16) * (int)sizeof(float);
    cudaFuncSetAttribute(gru_seq_kernel,
                         cudaFuncAttributeMaxDynamicSharedMemorySize,
                         smem_bytes);

    dim3 ggrid(GATES / BN, (NROWS + BM - 1) / BM);
    gi_gemm_kernel<<<ggrid, 256>>>(tokens, emb, w_ih, b_ih);

    gru_seq_kernel<<<NCTA, GT, smem_bytes>>>(w_hh, b_hh, out);
}

// round 10
// speedup vs baseline: 1.2266x; 1.1091x over previous
#include <cuda_runtime.h>
#include <cstdint>

// ---------------------------------------------------------------------------
// EncoderGRU: bidirectional GRU, SEQ=4096, HIDDEN=EMBED=1024.
//
//   Phase 1+2 (one kernel): GI[t] = w_ih @ emb[tok[t]] + b_ih, fp32 SIMT GEMM,
//            inline token prep + recurrent-state reset by block (0,0).
//   Phase 3: persistent kernel, 128 CTAs (64 fwd / 64 bwd), each CTA owns 16
//            hidden units (48 w_hh rows; 4/warp in registers, 2/warp in smem).
//            Sync protocol: round-7/9-proven shape. ONE change this round:
//            the poll backoff is a clock64()-calibrated ~350-cycle spin
//            instead of __nanosleep (whose real quantum is µs-scale and was
//            the prime suspect for the unexplained ~3500 cyc/step of detect
//            latency). All warps of a CTA poll together -> no producer
//            starvation; poll rate ~1/620cyc keeps the counter line under
//            L2 slice capacity.
//            Gate math: __expf-based tanh + __fdividef sigmoids (fast path).
// ---------------------------------------------------------------------------

#define VOCAB   50257
#define HID     1024
#define SEQ     4096
#define NROWS   (SEQ + 2)       // 4098: +SOS row, +EOS row
#define GATES   3072

#define NCTA    128             // persistent grid (1 CTA/SM)
#define UNITS   16              // hidden units per CTA (64 CTAs/dir * 16 = 1024)
#define RPC     48              // weight rows per CTA (3 gates * 16 units)
#define GT      256             // threads in recurrent kernel
#define RPW     6               // rows per warp (8 warps * 6 = 48)
#define RREG    4               // rows per warp held in registers
#define RSM     2               // rows per warp streamed from smem (RPW-RREG)

// ---- global scratch (allocation-free: __device__ globals) ----
__device__ __align__(16)  float g_GI[(size_t)NROWS * GATES];    // ~50 MB
__device__ __align__(16)  float g_h[2][2][HID];                 // [dir][buf][unit]
__device__ __align__(128) int   g_cnt[2][32];                   // one 128B line per dir

__device__ __forceinline__ int ldcg_int(const int* p) {
    int v;
    asm volatile("ld.global.cg.b32 %0, [%1];" : "=r"(v) : "l"(p));
    return v;
}

// Calibrated busy-wait: no memory traffic, bounded duration (SM clock cycles).
__device__ __forceinline__ void spin_cycles(long long n) {
    long long lim = clock64() + n;
    while (clock64() < lim) { }
}

// ---------------------------------------------------------------------------
// Phase 1+2: GI GEMM with inline token prep + state reset.
// C[m][n] = sum_k emb[tok[m]][k] * w_ih[n][k] + b_ih[n]
// BM=BN=128, BK=8, 256 threads, 8x8 microtile per thread.
// ---------------------------------------------------------------------------
#define BM 128
#define BN 128
#define BK 8

__global__ void __launch_bounds__(256) gi_gemm_kernel(
    const void*  __restrict__ tok_raw,
    const float* __restrict__ emb,
    const float* __restrict__ w_ih,
    const float* __restrict__ b_ih) {

    __shared__ float As[BK][BM];
    __shared__ float Bs[BK][BN];
    __shared__ int   mode64_sh;

    const int tid  = threadIdx.x;
    const int m0   = blockIdx.y * BM;
    const int n0   = blockIdx.x * BN;
    const int lrow = tid >> 1;          // 0..127
    const int lk   = (tid & 1) * 4;     // 0 or 4
    const int tx   = tid & 15;
    const int ty   = tid >> 4;

    // state reset (fresh every launch / graph replay) -- block (0,0) only
    if (blockIdx.x == 0 && blockIdx.y == 0) {
        for (int i = tid; i < 2 * 2 * HID; i += 256) ((float*)g_h)[i] = 0.f;
        if (tid < 64) ((int*)g_cnt)[tid] = 0;
    }

    // token dtype detection (per block; 8 loads, trivial)
    if (tid == 0) {
        // Genuine int64 tokens: every value < VOCAB (high word 0).
        // int32 data misread as int64: some 64-bit word >= VOCAB w.h.p.
        const unsigned long long* p = (const unsigned long long*)tok_raw;
        int m = 1;
        #pragma unroll
        for (int i = 0; i < 8; i++)
            if (p[i] >= (unsigned long long)VOCAB) m = 0;
        mode64_sh = m;
    }
    __syncthreads();
    const int mode64 = mode64_sh;

    // inline token fetch for this block's A row
    const int m = m0 + lrow;
    const float* arow_ptr = nullptr;
    if (m < NROWS) {
        int tok;
        if (m == SEQ)          tok = 0;   // SOS
        else if (m == SEQ + 1) tok = 1;   // EOS
        else tok = mode64 ? (int)((const long long*)tok_raw)[m]
                          : ((const int*)tok_raw)[m];
        arow_ptr = emb + (size_t)tok * HID;
    }
    const float* brow_ptr = w_ih + (size_t)(n0 + lrow) * HID;

    float acc[8][8];
    #pragma unroll
    for (int i = 0; i < 8; i++)
        #pragma unroll
        for (int j = 0; j < 8; j++) acc[i][j] = 0.f;

    for (int k0 = 0; k0 < HID; k0 += BK) {
        float4 a4 = make_float4(0.f, 0.f, 0.f, 0.f);
        if (arow_ptr) a4 = *(const float4*)(arow_ptr + k0 + lk);
        float4 b4 = *(const float4*)(brow_ptr + k0 + lk);
        As[lk + 0][lrow] = a4.x; As[lk + 1][lrow] = a4.y;
        As[lk + 2][lrow] = a4.z; As[lk + 3][lrow] = a4.w;
        Bs[lk + 0][lrow] = b4.x; Bs[lk + 1][lrow] = b4.y;
        Bs[lk + 2][lrow] = b4.z; Bs[lk + 3][lrow] = b4.w;
        __syncthreads();

        #pragma unroll
        for (int kk = 0; kk < BK; kk++) {
            float ra[8], rb[8];
            *(float4*)&ra[0] = *(const float4*)&As[kk][ty * 8];
            *(float4*)&ra[4] = *(const float4*)&As[kk][ty * 8 + 4];
            *(float4*)&rb[0] = *(const float4*)&Bs[kk][tx * 8];
            *(float4*)&rb[4] = *(const float4*)&Bs[kk][tx * 8 + 4];
            #pragma unroll
            for (int i = 0; i < 8; i++)
                #pragma unroll
                for (int j = 0; j < 8; j++)
                    acc[i][j] += ra[i] * rb[j];
        }
        __syncthreads();
    }

    float bias[8];
    *(float4*)&bias[0] = *(const float4*)(b_ih + n0 + tx * 8);
    *(float4*)&bias[4] = *(const float4*)(b_ih + n0 + tx * 8 + 4);

    #pragma unroll
    for (int i = 0; i < 8; i++) {
        int mm = m0 + ty * 8 + i;
        if (mm < NROWS) {
            float* gp = g_GI + (size_t)mm * GATES + n0 + tx * 8;
            float4 v0 = make_float4(acc[i][0] + bias[0], acc[i][1] + bias[1],
                                    acc[i][2] + bias[2], acc[i][3] + bias[3]);
            float4 v1 = make_float4(acc[i][4] + bias[4], acc[i][5] + bias[5],
                                    acc[i][6] + bias[6], acc[i][7] + bias[7]);
            *(float4*)gp       = v0;
            *(float4*)(gp + 4) = v1;
        }
    }
}

// ---------------------------------------------------------------------------
// Phase 3: persistent recurrent kernel.
// Weight rows per warp: rows 0..3 in registers, rows 4..5 in smem.
// Global row for local row rr (0..47): ((rr>>4)<<10) + u0 + (rr&15).
// ---------------------------------------------------------------------------
__global__ void __launch_bounds__(GT, 1) gru_seq_kernel(
    const float* __restrict__ w_hh,
    const float* __restrict__ b_hh,
    float* __restrict__ out) {

    extern __shared__ float smem[];
    float* wsh  = smem;                 // 16 rows (2/warp) * HID
    float* bsh  = smem + (RSM * 8) * HID;   // RPC biases
    float* sums = bsh + RPC;            // RPC partial sums

    const int cta  = blockIdx.x;
    const int dir  = cta >> 6;          // 0 = forward, 1 = backward
    const int lcta = cta & 63;
    const int u0   = lcta * UNITS;
    const int warp = threadIdx.x >> 5;
    const int lane = threadIdx.x & 31;

    // --- smem rows: local rows {w*6+4, w*6+5} stored at smem row (w*2 + sub)
    for (int i = threadIdx.x; i < RSM * 8 * HID; i += GT) {
        int mrow = i >> 10;             // 0..15
        int c    = i & (HID - 1);
        int rr   = (mrow >> 1) * RPW + RREG + (mrow & 1);
        int grow = ((rr >> 4) << 10) + u0 + (rr & 15);
        wsh[i] = w_hh[(size_t)grow * HID + c];
    }
    if (threadIdx.x < RPC) {
        int rr = threadIdx.x;
        bsh[rr] = b_hh[((rr >> 4) << 10) + u0 + (rr & 15)];
    }

    // --- register rows: warp's local rows 0..3, this lane's 32 columns
    float4 wreg[RREG][8];
    #pragma unroll
    for (int r = 0; r < RREG; r++) {
        const int rr   = warp * RPW + r;
        const int grow = ((rr >> 4) << 10) + u0 + (rr & 15);
        const float* gw = w_hh + (size_t)grow * HID + lane * 4;
        #pragma unroll
        for (int j = 0; j < 8; j++)
            wreg[r][j] = *(const float4*)(gw + j * 128);
    }
    __syncthreads();

    const float* wp = wsh + (warp * RSM) * HID + lane * 4;  // smem rows 4..5
    const int* cnt_p = &g_cnt[dir][0];

    float hprev = 0.f;                  // held by threads < UNITS only

    for (int s = 0; s <= SEQ; s++) {
        const int t     = dir ? (SEQ - s) : (s - 1);
        const int girow = (s == 0) ? (SEQ + dir) : t;

        // gi prefetch (independent of h; overlaps the poll below)
        float gir = 0.f, giz = 0.f, gin = 0.f;
        if (threadIdx.x < UNITS) {
            const float* gp = g_GI + (size_t)girow * GATES + u0 + threadIdx.x;
            gir = __ldg(gp);
            giz = __ldg(gp + HID);
            gin = __ldg(gp + 2 * HID);
        }

        // Wait until all 64 CTAs of this direction finished step s-1.
        // EVERY thread observes the counter itself (broadcast 4B sector) and
        // fences itself -- the proven acquire pattern (r5/r7/r9). Backoff is
        // a calibrated ~350-cycle clock spin (no memory traffic) instead of
        // __nanosleep: bounded, known poll period, no sleep-quantum penalty.
        if (s > 0) {
            const int need = s << 6;    // 64 * s
            if (ldcg_int(cnt_p) < need) {
                do { spin_cycles(350); } while (ldcg_int(cnt_p) < need);
            }
            __threadfence();            // acquire (per-thread)
        }

        // load broadcast h (L2: written by other SMs last step)
        const float4* hp = (const float4*)(&g_h[dir][s & 1][0]) + lane;
        float4 h4[8];
        #pragma unroll
        for (int j = 0; j < 8; j++) h4[j] = __ldcg(hp + 32 * j);

        // 6 dot products per warp: rows 0..3 from registers, 4..5 from smem
        float acc[RPW] = {0.f, 0.f, 0.f, 0.f, 0.f, 0.f};
        #pragma unroll
        for (int j = 0; j < 8; j++) {
            const float4 hv = h4[j];
            #pragma unroll
            for (int r = 0; r < RREG; r++) {
                const float4 wv = wreg[r][j];
                acc[r] += hv.x * wv.x;
                acc[r] += hv.y * wv.y;
                acc[r] += hv.z * wv.z;
                acc[r] += hv.w * wv.w;
            }
            #pragma unroll
            for (int r = 0; r < RSM; r++) {
                const float4 wv = *(const float4*)(wp + r * HID + j * 128);
                acc[RREG + r] += hv.x * wv.x;
                acc[RREG + r] += hv.y * wv.y;
                acc[RREG + r] += hv.z * wv.z;
                acc[RREG + r] += hv.w * wv.w;
            }
        }
        #pragma unroll
        for (int r = 0; r < RPW; r++) {
            float v = acc[r];
            v += __shfl_xor_sync(0xffffffffu, v, 16);
            v += __shfl_xor_sync(0xffffffffu, v, 8);
            v += __shfl_xor_sync(0xffffffffu, v, 4);
            v += __shfl_xor_sync(0xffffffffu, v, 2);
            v += __shfl_xor_sync(0xffffffffu, v, 1);
            if (lane == 0) sums[warp * RPW + r] = v;
        }
        __syncthreads();                // sums ready

        if (threadIdx.x < UNITS) {
            const int i = threadIdx.x;
            const int u = u0 + i;
            // fast gates: __expf (MUFU) + approx division; error ~2^-21,
            // far inside the 1e-3 harness threshold.
            float ar = gir + sums[i]      + bsh[i];
            float az = giz + sums[16 + i] + bsh[16 + i];
            float rg = __fdividef(1.f, 1.f + __expf(-ar));
            float zg = __fdividef(1.f, 1.f + __expf(-az));
            float an = gin + rg * (sums[32 + i] + bsh[32 + i]);
            float en = __expf(-2.f * an);
            float ng = __fdividef(1.f - en, 1.f + en);   // tanh(an)
            float hn = (1.f - zg) * ng + zg * hprev;
            hprev = hn;
            __stcg(&g_h[dir][(s + 1) & 1][u], hn);
            if (s >= 1) {
                // hiddens[t] = [hs_f[t] | hs_b[t]], after h_b (1024 floats)
                out[(size_t)HID + (size_t)t * (2 * HID) + dir * HID + u] = hn;
                if (dir == 1 && t == 0) out[u] = hn;   // h_b = hs_b[0]
            }
        }
        __syncthreads();                // h writes CTA-visible (r7 pattern)
        if (threadIdx.x == 0) {
            __threadfence();            // cumulative release: h before counter
            atomicAdd(&g_cnt[dir][0], 1);  // REDG (result unused)
        }
    }
}

// ---------------------------------------------------------------------------
// launch
// ---------------------------------------------------------------------------
extern "C" void kernel_launch(void* const* d_in, const int* in_sizes, int n_in,
                              void* d_out, int out_size) {
    const void*  tokens = d_in[0];
    const float* emb    = (const float*)d_in[1];
    const float* w_ih   = (const float*)d_in[2];
    const float* w_hh   = (const float*)d_in[3];
    const float* b_ih   = (const float*)d_in[4];
    const float* b_hh   = (const float*)d_in[5];
    float* out = (float*)d_out;

    const int smem_bytes = (RSM * 8 * HID + 2 * RPC + 16) * (int)sizeof(float);
    cudaFuncSetAttribute(gru_seq_kernel,
                         cudaFuncAttributeMaxDynamicSharedMemorySize,
                         smem_bytes);

    dim3 ggrid(GATES / BN, (NROWS + BM - 1) / BM);
    gi_gemm_kernel<<<ggrid, 256>>>(tokens, emb, w_ih, b_ih);

    gru_seq_kernel<<<NCTA, GT, smem_bytes>>>(w_hh, b_hh, out);
}